// round 2
// baseline (speedup 1.0000x reference)
#include <cuda_runtime.h>

// Problem constants (fixed by the reference)
#define BATCH   32
#define DIM     256          // embedding dim (C)
#define HW      1024         // H*W = 32*32
#define NROWS   32768        // BATCH*HW flattened pixels
#define KCB     1024         // codebook entries
#define NQ      (NROWS * DIM)   // 8,388,608 quantized elements

// Device scratch (static globals — no allocation)
__device__ float g_Et[DIM * KCB];        // embedding transposed: [d][k]
__device__ float g_C[KCB];               // sum(e*e) per code (XLA-order emu)
__device__ float g_xx[NROWS];            // sum(x*x) per row (XLA-order emu)
__device__ int   g_idx[NROWS];           // argmin index per pixel
__device__ float g_partial[BATCH * DIM]; // per-(b,d) loss partials

// ---------------------------------------------------------------------------
// Prep 1: transpose embedding [K,D] -> [D,K]
// ---------------------------------------------------------------------------
__global__ void transpose_emb(const float* __restrict__ E) {
    __shared__ float tile[32][33];
    int k0 = blockIdx.x * 32;
    int d0 = blockIdx.y * 32;
    int tx = threadIdx.x;
    int ty = threadIdx.y;
#pragma unroll
    for (int i = 0; i < 32; i += 8)
        tile[ty + i][tx] = E[(size_t)(k0 + ty + i) * DIM + d0 + tx];
    __syncthreads();
#pragma unroll
    for (int i = 0; i < 32; i += 8)
        g_Et[(size_t)(d0 + ty + i) * KCB + k0 + tx] = tile[tx][ty + i];
}

// ---------------------------------------------------------------------------
// Prep 2: C_k = sum_d e^2, sequential d-ascending, UNFUSED mul/add
// (emulates XLA CPU scalar reduce of multiply(e,e)).
// ---------------------------------------------------------------------------
__global__ void csum_kernel(const float* __restrict__ E) {
    int k = blockIdx.x * 256 + threadIdx.x;
    const float* row = E + (size_t)k * DIM;
    float a = 0.f;
    for (int d = 0; d < DIM; d++)
        a = __fadd_rn(a, __fmul_rn(row[d], row[d]));
    g_C[k] = a;
}

// ---------------------------------------------------------------------------
// Prep 3: A_n = sum_d x^2, sequential d-ascending, UNFUSED mul/add.
// This value reaches ~256 so its exact rounding sequence decides argmin ties;
// hypothesis A1 = scalar sequential (XLA CPU elemental emitter).
// ---------------------------------------------------------------------------
__global__ void xx_kernel(const float* __restrict__ X) {
    int n = blockIdx.x * 256 + threadIdx.x;
    int b = n >> 10, hw = n & (HW - 1);
    const float* p = X + (size_t)b * DIM * HW + hw;
    float a = 0.f;
    for (int d = 0; d < DIM; d++) {
        float v = p[(size_t)d * HW];
        a = __fadd_rn(a, __fmul_rn(v, v));
    }
    g_xx[n] = a;
}

// ---------------------------------------------------------------------------
// Main: fused SGEMM (T = X·E^T, fp32 FFMA chain, d ascending) + argmin over
// d_k = fl(fl(A - 2T) + C)  — the reference's exact fp32 expression.
// Ties resolve to the lowest k (ascending scan + strict <).
// Block tile: 128 rows x 128 codes, 8x8 register micro-tile, d-chunks of 16.
// grid NROWS/128 = 256, block 256 threads.
// ---------------------------------------------------------------------------
__global__ __launch_bounds__(256, 2)
void vq_argmin(const float* __restrict__ X) {
    __shared__ float Xs[16][128];
    __shared__ float Es[16][128];
    __shared__ float cn[KCB];
    __shared__ float rv[128][17];
    __shared__ int   ri[128][17];

    const int tid = threadIdx.x;
    const int tx = tid & 15;
    const int ty = tid >> 4;
    const int row0 = blockIdx.x * 128;
    const int b   = row0 / HW;
    const int hw0 = row0 % HW;
    const float* Xbase = X + (size_t)b * DIM * HW + hw0;

    for (int i = tid; i < KCB; i += 256) cn[i] = g_C[i];

    float av[8];
#pragma unroll
    for (int r = 0; r < 8; r++) av[r] = g_xx[row0 + ty * 8 + r];

    float bv[8]; int bi[8];
#pragma unroll
    for (int r = 0; r < 8; r++) { bv[r] = 3.4e38f; bi[r] = 0; }

    const int ld = tid >> 5;
    const int l4 = tid & 31;

    for (int kt = 0; kt < KCB; kt += 128) {
        float acc[8][8];
#pragma unroll
        for (int r = 0; r < 8; r++)
#pragma unroll
            for (int c = 0; c < 8; c++) acc[r][c] = 0.f;

        for (int dc = 0; dc < DIM; dc += 16) {
            __syncthreads();
            *((float4*)&Xs[ld][l4 * 4]) =
                *((const float4*)(Xbase + (size_t)(dc + ld) * HW) + l4);
            *((float4*)&Xs[ld + 8][l4 * 4]) =
                *((const float4*)(Xbase + (size_t)(dc + ld + 8) * HW) + l4);
            *((float4*)&Es[ld][l4 * 4]) =
                *((const float4*)(g_Et + (size_t)(dc + ld) * KCB + kt) + l4);
            *((float4*)&Es[ld + 8][l4 * 4]) =
                *((const float4*)(g_Et + (size_t)(dc + ld + 8) * KCB + kt) + l4);
            __syncthreads();

#pragma unroll
            for (int dd = 0; dd < 16; dd++) {
                float xr[8], er[8];
                *(float4*)&xr[0] = *(float4*)&Xs[dd][ty * 8];
                *(float4*)&xr[4] = *(float4*)&Xs[dd][ty * 8 + 4];
                *(float4*)&er[0] = *(float4*)&Es[dd][tx * 8];
                *(float4*)&er[4] = *(float4*)&Es[dd][tx * 8 + 4];
#pragma unroll
                for (int r = 0; r < 8; r++)
#pragma unroll
                    for (int c = 0; c < 8; c++)
                        acc[r][c] = __fmaf_rn(xr[r], er[c], acc[r][c]);
            }
        }
        // argmin epilogue: replicate ref's rounding d = fl(fl(A-2T)+C)
#pragma unroll
        for (int c = 0; c < 8; c++) {
            int k = kt + tx * 8 + c;
            float cc = cn[k];
#pragma unroll
            for (int r = 0; r < 8; r++) {
                float v = __fadd_rn(__fsub_rn(av[r], 2.0f * acc[r][c]), cc);
                if (v < bv[r]) { bv[r] = v; bi[r] = k; }
            }
        }
    }

    __syncthreads();
#pragma unroll
    for (int r = 0; r < 8; r++) { rv[ty * 8 + r][tx] = bv[r]; ri[ty * 8 + r][tx] = bi[r]; }
    __syncthreads();
    if (tid < 128) {
        float best = rv[tid][0]; int besti = ri[tid][0];
#pragma unroll
        for (int t = 1; t < 16; t++) {
            float v = rv[tid][t]; int ii = ri[tid][t];
            if (v < best || (v == best && ii < besti)) { best = v; besti = ii; }
        }
        g_idx[row0 + tid] = besti;
    }
}

// ---------------------------------------------------------------------------
// Epilogue: gather quantized values, straight-through output replicated as
// fl(x + fl(q - x)), per-(b,d) loss partials on fl(q-x)^2, indices as float.
// ---------------------------------------------------------------------------
__global__ void vq_epilogue(const float* __restrict__ X,
                            float* __restrict__ out, int write_extra) {
    const int bo = blockIdx.x;          // b*DIM + d
    const int b = bo >> 8, d = bo & 255;
    const int tid = threadIdx.x;
    const size_t base = (size_t)bo * HW;
    const int nbase = b * HW;

    float4 x = ((const float4*)(X + base))[tid];
    int i0 = g_idx[nbase + tid * 4 + 0];
    int i1 = g_idx[nbase + tid * 4 + 1];
    int i2 = g_idx[nbase + tid * 4 + 2];
    int i3 = g_idx[nbase + tid * 4 + 3];
    const float* Erow = g_Et + (size_t)d * KCB;
    float q0 = Erow[i0], q1 = Erow[i1], q2 = Erow[i2], q3 = Erow[i3];

    // ref: diff = fl(q - x); st = fl(x + diff); loss term fl(diff^2)
    float s0 = __fsub_rn(q0, x.x), s1 = __fsub_rn(q1, x.y);
    float s2 = __fsub_rn(q2, x.z), s3 = __fsub_rn(q3, x.w);
    float4 o;
    o.x = __fadd_rn(x.x, s0); o.y = __fadd_rn(x.y, s1);
    o.z = __fadd_rn(x.z, s2); o.w = __fadd_rn(x.w, s3);
    ((float4*)(out + base))[tid] = o;

    __shared__ float red[256];
    red[tid] = __fmul_rn(s0, s0) + __fmul_rn(s1, s1)
             + __fmul_rn(s2, s2) + __fmul_rn(s3, s3);
    __syncthreads();
#pragma unroll
    for (int o2 = 128; o2; o2 >>= 1) { if (tid < o2) red[tid] += red[tid + o2]; __syncthreads(); }
    if (tid == 0) g_partial[bo] = red[0];

    if (write_extra && d == 0) {
        float* iout = out + (size_t)NQ + 1 + nbase;
        iout[tid * 4 + 0] = (float)i0;
        iout[tid * 4 + 1] = (float)i1;
        iout[tid * 4 + 2] = (float)i2;
        iout[tid * 4 + 3] = (float)i3;
    }
}

// ---------------------------------------------------------------------------
// Deterministic loss reduction: loss = 1.25 * mean((q - x)^2)
// (mean divide by NQ = 2^23 is exact; 1.25*e == fl(e + 0.25e))
// ---------------------------------------------------------------------------
__global__ void vq_finalize(float* __restrict__ out) {
    __shared__ float red[1024];
    int tid = threadIdx.x;
    float s = 0.f;
#pragma unroll
    for (int i = tid; i < BATCH * DIM; i += 1024) s += g_partial[i];
    red[tid] = s;
    __syncthreads();
#pragma unroll
    for (int o = 512; o; o >>= 1) { if (tid < o) red[tid] += red[tid + o]; __syncthreads(); }
    if (tid == 0) out[(size_t)NQ] = 1.25f * (red[0] / (float)NQ);
}

extern "C" void kernel_launch(void* const* d_in, const int* in_sizes, int n_in,
                              void* d_out, int out_size) {
    const float* X = (const float*)d_in[0];   // inputs [32,256,32,32] f32
    const float* E = (const float*)d_in[1];   // embedding [1024,256] f32
    float* out = (float*)d_out;

    transpose_emb<<<dim3(KCB / 32, DIM / 32), dim3(32, 8)>>>(E);
    csum_kernel<<<KCB / 256, 256>>>(E);
    xx_kernel<<<NROWS / 256, 256>>>(X);
    vq_argmin<<<NROWS / 128, 256>>>(X);

    int write_extra = (out_size >= NQ + 1 + NROWS) ? 1 : 0;
    vq_epilogue<<<BATCH * DIM, 256>>>(X, out, write_extra);
    if (out_size > NQ) vq_finalize<<<1, 1024>>>(out);
}

// round 3
// speedup vs baseline: 1.1640x; 1.1640x over previous
#include <cuda_runtime.h>

// Problem constants (fixed by the reference)
#define BATCH   32
#define DIM     256          // embedding dim (C)
#define HW      1024         // H*W = 32*32
#define NROWS   32768        // BATCH*HW flattened pixels
#define KCB     1024         // codebook entries
#define NQ      (NROWS * DIM)   // 8,388,608 quantized elements
#define NQUART  4            // codebook split for wave balance
#define KQ      (KCB / NQUART)  // 256 codes per quarter

// Device scratch (static globals — no allocation)
__device__ float g_Et[DIM * KCB];        // embedding transposed: [d][k]
__device__ float g_C[KCB];               // sum(e*e) per code (XLA-order emu)
__device__ float g_xx[NROWS];            // sum(x*x) per row (XLA-order emu)
__device__ int   g_idx[NROWS];           // argmin index per pixel
__device__ float g_partial[BATCH * DIM]; // per-(b,d) loss partials
__device__ float g_pbv[NQUART][NROWS];   // per-quarter best value
__device__ int   g_pbi[NQUART][NROWS];   // per-quarter best index

// Packed fp32x2 FMA: d = a*b + d  (2 FMAs / instruction, fma pipe)
__device__ __forceinline__ void ffma2(unsigned long long& d,
                                      unsigned long long a,
                                      unsigned long long b) {
    asm("fma.rn.f32x2 %0, %1, %2, %0;" : "+l"(d) : "l"(a), "l"(b));
}
__device__ __forceinline__ unsigned long long dup2(float x) {
    unsigned long long r;
    asm("mov.b64 %0, {%1, %1};" : "=l"(r) : "f"(x));
    return r;
}
__device__ __forceinline__ void unpack2(float& lo, float& hi, unsigned long long v) {
    asm("mov.b64 {%0, %1}, %2;" : "=f"(lo), "=f"(hi) : "l"(v));
}

// ---------------------------------------------------------------------------
// Prep 1: transpose embedding [K,D] -> [D,K]
// ---------------------------------------------------------------------------
__global__ void transpose_emb(const float* __restrict__ E) {
    __shared__ float tile[32][33];
    int k0 = blockIdx.x * 32;
    int d0 = blockIdx.y * 32;
    int tx = threadIdx.x;
    int ty = threadIdx.y;
#pragma unroll
    for (int i = 0; i < 32; i += 8)
        tile[ty + i][tx] = E[(size_t)(k0 + ty + i) * DIM + d0 + tx];
    __syncthreads();
#pragma unroll
    for (int i = 0; i < 32; i += 8)
        g_Et[(size_t)(d0 + ty + i) * KCB + k0 + tx] = tile[tx][ty + i];
}

// ---------------------------------------------------------------------------
// Prep 2: C_k = sum_d e^2, sequential d-ascending, UNFUSED mul/add
// (bit-exact emulation of the reference reduce).
// ---------------------------------------------------------------------------
__global__ void csum_kernel(const float* __restrict__ E) {
    int k = blockIdx.x * 256 + threadIdx.x;
    const float* row = E + (size_t)k * DIM;
    float a = 0.f;
    for (int d = 0; d < DIM; d++)
        a = __fadd_rn(a, __fmul_rn(row[d], row[d]));
    g_C[k] = a;
}

// ---------------------------------------------------------------------------
// Prep 3: A_n = sum_d x^2, sequential d-ascending, UNFUSED mul/add.
// Its exact rounding sequence decides argmin ties — verified bit-exact.
// ---------------------------------------------------------------------------
__global__ void xx_kernel(const float* __restrict__ X) {
    int n = blockIdx.x * 256 + threadIdx.x;
    int b = n >> 10, hw = n & (HW - 1);
    const float* p = X + (size_t)b * DIM * HW + hw;
    float a = 0.f;
    for (int d = 0; d < DIM; d++) {
        float v = p[(size_t)d * HW];
        a = __fadd_rn(a, __fmul_rn(v, v));
    }
    g_xx[n] = a;
}

// ---------------------------------------------------------------------------
// Main: fused SGEMM (T = X·E^T, packed f32x2 FMA) + argmin over
// d_k = fl(fl(A - 2T) + C).  Ties resolve to the lowest k.
// grid = 256 row-tiles x 4 k-quarters = 1024 blocks (wave-balanced).
// Each block: 128 rows x 256 codes (2 kt-iterations of 128 codes),
// 8 rows x 8 codes per thread (codes packed as 4 f32x2 pairs).
// ---------------------------------------------------------------------------
__global__ __launch_bounds__(256, 2)
void vq_argmin(const float* __restrict__ X) {
    __shared__ float Xs[16][128];
    __shared__ float Es[16][128];
    __shared__ float cn[KQ];
    __shared__ float rv[128][17];
    __shared__ int   ri[128][17];

    const int tid = threadIdx.x;
    const int tx = tid & 15;          // code sub-tile (16 x 8 codes)
    const int ty = tid >> 4;          // row sub-tile (16 x 8 rows)
    const int rt = blockIdx.x >> 2;   // row-tile 0..255
    const int q  = blockIdx.x & 3;    // codebook quarter
    const int kbase = q * KQ;
    const int row0 = rt * 128;
    const int b   = row0 / HW;
    const int hw0 = row0 % HW;
    const float* Xbase = X + (size_t)b * DIM * HW + hw0;

    for (int i = tid; i < KQ; i += 256) cn[i] = g_C[kbase + i];

    float av[8];
#pragma unroll
    for (int r = 0; r < 8; r++) av[r] = g_xx[row0 + ty * 8 + r];

    float bv[8]; int bi[8];
#pragma unroll
    for (int r = 0; r < 8; r++) { bv[r] = 3.4e38f; bi[r] = 0; }

    const int ld = tid >> 5;
    const int l4 = tid & 31;

    for (int kt = kbase; kt < kbase + KQ; kt += 128) {
        unsigned long long acc2[8][4];
#pragma unroll
        for (int r = 0; r < 8; r++)
#pragma unroll
            for (int c = 0; c < 4; c++) acc2[r][c] = 0ull;

        for (int dc = 0; dc < DIM; dc += 16) {
            __syncthreads();
            *((float4*)&Xs[ld][l4 * 4]) =
                *((const float4*)(Xbase + (size_t)(dc + ld) * HW) + l4);
            *((float4*)&Xs[ld + 8][l4 * 4]) =
                *((const float4*)(Xbase + (size_t)(dc + ld + 8) * HW) + l4);
            *((float4*)&Es[ld][l4 * 4]) =
                *((const float4*)(g_Et + (size_t)(dc + ld) * KCB + kt) + l4);
            *((float4*)&Es[ld + 8][l4 * 4]) =
                *((const float4*)(g_Et + (size_t)(dc + ld + 8) * KCB + kt) + l4);
            __syncthreads();

#pragma unroll
            for (int dd = 0; dd < 16; dd++) {
                float xr[8];
                *(float4*)&xr[0] = *(float4*)&Xs[dd][ty * 8];
                *(float4*)&xr[4] = *(float4*)&Xs[dd][ty * 8 + 4];
                ulonglong2 e01 = *(ulonglong2*)&Es[dd][tx * 8];
                ulonglong2 e23 = *(ulonglong2*)&Es[dd][tx * 8 + 4];
                unsigned long long er2[4] = {e01.x, e01.y, e23.x, e23.y};
                unsigned long long xr2[8];
#pragma unroll
                for (int r = 0; r < 8; r++) xr2[r] = dup2(xr[r]);
#pragma unroll
                for (int r = 0; r < 8; r++)
#pragma unroll
                    for (int c = 0; c < 4; c++)
                        ffma2(acc2[r][c], xr2[r], er2[c]);
            }
        }
        // argmin epilogue: replicate ref's rounding d = fl(fl(A-2T)+C)
#pragma unroll
        for (int c = 0; c < 4; c++) {
            int k0 = kt + tx * 8 + 2 * c;
            float c0 = cn[k0 - kbase];
            float c1 = cn[k0 + 1 - kbase];
#pragma unroll
            for (int r = 0; r < 8; r++) {
                float t0, t1;
                unpack2(t0, t1, acc2[r][c]);
                float v0 = __fadd_rn(__fsub_rn(av[r], 2.0f * t0), c0);
                float v1 = __fadd_rn(__fsub_rn(av[r], 2.0f * t1), c1);
                if (v0 < bv[r]) { bv[r] = v0; bi[r] = k0; }
                if (v1 < bv[r]) { bv[r] = v1; bi[r] = k0 + 1; }
            }
        }
    }

    __syncthreads();
#pragma unroll
    for (int r = 0; r < 8; r++) { rv[ty * 8 + r][tx] = bv[r]; ri[ty * 8 + r][tx] = bi[r]; }
    __syncthreads();
    if (tid < 128) {
        float best = rv[tid][0]; int besti = ri[tid][0];
#pragma unroll
        for (int t = 1; t < 16; t++) {
            float v = rv[tid][t]; int ii = ri[tid][t];
            if (v < best || (v == best && ii < besti)) { best = v; besti = ii; }
        }
        g_pbv[q][row0 + tid] = best;
        g_pbi[q][row0 + tid] = besti;
    }
}

// ---------------------------------------------------------------------------
// Merge the 4 per-quarter candidates (ascending k order + strict < keeps
// the lowest index on exact ties, matching jnp.argmin).
// ---------------------------------------------------------------------------
__global__ void vq_merge() {
    int n = blockIdx.x * 256 + threadIdx.x;
    float best = g_pbv[0][n]; int besti = g_pbi[0][n];
#pragma unroll
    for (int q = 1; q < NQUART; q++) {
        float v = g_pbv[q][n];
        if (v < best) { best = v; besti = g_pbi[q][n]; }
    }
    g_idx[n] = besti;
}

// ---------------------------------------------------------------------------
// Epilogue: gather quantized values, straight-through output replicated as
// fl(x + fl(q - x)), per-(b,d) loss partials on fl(q-x)^2, indices as float.
// ---------------------------------------------------------------------------
__global__ void vq_epilogue(const float* __restrict__ X,
                            float* __restrict__ out, int write_extra) {
    const int bo = blockIdx.x;          // b*DIM + d
    const int b = bo >> 8, d = bo & 255;
    const int tid = threadIdx.x;
    const size_t base = (size_t)bo * HW;
    const int nbase = b * HW;

    float4 x = ((const float4*)(X + base))[tid];
    int i0 = g_idx[nbase + tid * 4 + 0];
    int i1 = g_idx[nbase + tid * 4 + 1];
    int i2 = g_idx[nbase + tid * 4 + 2];
    int i3 = g_idx[nbase + tid * 4 + 3];
    const float* Erow = g_Et + (size_t)d * KCB;
    float q0 = Erow[i0], q1 = Erow[i1], q2 = Erow[i2], q3 = Erow[i3];

    float s0 = __fsub_rn(q0, x.x), s1 = __fsub_rn(q1, x.y);
    float s2 = __fsub_rn(q2, x.z), s3 = __fsub_rn(q3, x.w);
    float4 o;
    o.x = __fadd_rn(x.x, s0); o.y = __fadd_rn(x.y, s1);
    o.z = __fadd_rn(x.z, s2); o.w = __fadd_rn(x.w, s3);
    ((float4*)(out + base))[tid] = o;

    __shared__ float red[256];
    red[tid] = __fmul_rn(s0, s0) + __fmul_rn(s1, s1)
             + __fmul_rn(s2, s2) + __fmul_rn(s3, s3);
    __syncthreads();
#pragma unroll
    for (int o2 = 128; o2; o2 >>= 1) { if (tid < o2) red[tid] += red[tid + o2]; __syncthreads(); }
    if (tid == 0) g_partial[bo] = red[0];

    if (write_extra && d == 0) {
        float* iout = out + (size_t)NQ + 1 + nbase;
        iout[tid * 4 + 0] = (float)i0;
        iout[tid * 4 + 1] = (float)i1;
        iout[tid * 4 + 2] = (float)i2;
        iout[tid * 4 + 3] = (float)i3;
    }
}

// ---------------------------------------------------------------------------
// Deterministic loss reduction: loss = 1.25 * mean((q - x)^2)
// ---------------------------------------------------------------------------
__global__ void vq_finalize(float* __restrict__ out) {
    __shared__ float red[1024];
    int tid = threadIdx.x;
    float s = 0.f;
#pragma unroll
    for (int i = tid; i < BATCH * DIM; i += 1024) s += g_partial[i];
    red[tid] = s;
    __syncthreads();
#pragma unroll
    for (int o = 512; o; o >>= 1) { if (tid < o) red[tid] += red[tid + o]; __syncthreads(); }
    if (tid == 0) out[(size_t)NQ] = 1.25f * (red[0] / (float)NQ);
}

extern "C" void kernel_launch(void* const* d_in, const int* in_sizes, int n_in,
                              void* d_out, int out_size) {
    const float* X = (const float*)d_in[0];   // inputs [32,256,32,32] f32
    const float* E = (const float*)d_in[1];   // embedding [1024,256] f32
    float* out = (float*)d_out;

    transpose_emb<<<dim3(KCB / 32, DIM / 32), dim3(32, 8)>>>(E);
    csum_kernel<<<KCB / 256, 256>>>(E);
    xx_kernel<<<NROWS / 256, 256>>>(X);
    vq_argmin<<<(NROWS / 128) * NQUART, 256>>>(X);
    vq_merge<<<NROWS / 256, 256>>>();

    int write_extra = (out_size >= NQ + 1 + NROWS) ? 1 : 0;
    vq_epilogue<<<BATCH * DIM, 256>>>(X, out, write_extra);
    if (out_size > NQ) vq_finalize<<<1, 1024>>>(out);
}